// round 9
// baseline (speedup 1.0000x reference)
#include <cuda_runtime.h>
#include <cstdint>
#include <cstddef>

#define SEQ   512
#define BATCH 64
#define INDIM 512
#define HID   1024
#define NCTA  128
#define CLUSTER 4

#define TILE_F   (64 * 68)          // floats per padded k-tile (64 rows x 68)
#define TILE_B   (TILE_F * 4)       // 17408 bytes
#define NTILE    16                 // 16 k-tiles of 64 cover K=1024

// ---------------- device scratch ----------------
__device__ float g_xproj[(size_t)SEQ * 3 * BATCH * HID];   // [s][gate][b][j]
__device__ float g_h[BATCH * HID];                         // exact fp32 hidden (linear)
__device__ __align__(128) float g_ht_t[NTILE * TILE_F];    // tf32 hidden, tiled+padded
__device__ __align__(128) float g_rh_t[NTILE * TILE_F];    // tf32 r*h,  tiled+padded
__device__ float g_z[BATCH * HID];
__device__ unsigned g_count;

// ---------------- helpers ----------------
__device__ __forceinline__ float to_tf32(float x) {
    uint32_t u;
    asm("cvt.rna.tf32.f32 %0, %1;" : "=r"(u) : "f"(x));
    return __uint_as_float(u);
}

__device__ __forceinline__ void mma_tf32(float c[4], const float a[4], const float b[2]) {
    asm volatile(
        "mma.sync.aligned.m16n8k8.row.col.f32.tf32.tf32.f32 "
        "{%0,%1,%2,%3}, {%4,%5,%6,%7}, {%8,%9}, {%0,%1,%2,%3};\n"
        : "+f"(c[0]), "+f"(c[1]), "+f"(c[2]), "+f"(c[3])
        : "r"(__float_as_uint(a[0])), "r"(__float_as_uint(a[1])),
          "r"(__float_as_uint(a[2])), "r"(__float_as_uint(a[3])),
          "r"(__float_as_uint(b[0])), "r"(__float_as_uint(b[1])));
}

__device__ __forceinline__ float sigmoidf_(float x) {
    return 1.0f / (1.0f + __expf(-x));
}

__device__ __forceinline__ void mbar_init(unsigned addr, unsigned cnt) {
    asm volatile("mbarrier.init.shared.b64 [%0], %1;" :: "r"(addr), "r"(cnt) : "memory");
}
__device__ __forceinline__ void mbar_expect_tx(unsigned addr, unsigned tx) {
    asm volatile("mbarrier.arrive.expect_tx.shared.b64 _, [%0], %1;"
                 :: "r"(addr), "r"(tx) : "memory");
}
__device__ __forceinline__ void mbar_arrive_cluster(unsigned local_addr, unsigned rank) {
    asm volatile(
        "{\n\t.reg .b32 ra;\n\t"
        "mapa.shared::cluster.u32 ra, %0, %1;\n\t"
        "mbarrier.arrive.shared::cluster.b64 _, [ra];\n\t}"
        :: "r"(local_addr), "r"(rank) : "memory");
}
__device__ __forceinline__ void mbar_wait(unsigned addr, unsigned parity) {
    asm volatile(
        "{\n\t.reg .pred P;\n\t"
        "LW%=:\n\t"
        "mbarrier.try_wait.parity.shared.b64 P, [%0], %1;\n\t"
        "@P bra.uni LD%=;\n\t"
        "bra.uni LW%=;\n\t"
        "LD%=:\n\t}"
        :: "r"(addr), "r"(parity) : "memory");
}
// multicast bulk copy: data + complete_tx delivered to the same SMEM offset
// in every cluster CTA whose bit is set in the mask.
__device__ __forceinline__ void bulk_cp_mc(float* dst_smem, const float* src,
                                           unsigned bytes, unsigned mbar) {
    unsigned d = (unsigned)__cvta_generic_to_shared(dst_smem);
    asm volatile(
        "cp.async.bulk.shared::cluster.global.mbarrier::complete_tx::bytes.multicast::cluster "
        "[%0], [%1], %2, [%3], %4;"
        :: "r"(d), "l"(src), "r"(bytes), "r"(mbar),
           "h"((unsigned short)0xF) : "memory");
}

#define CLUSTER_SYNC_() do { \
    asm volatile("barrier.cluster.arrive.aligned;" ::: "memory"); \
    asm volatile("barrier.cluster.wait.aligned;" ::: "memory"); \
} while (0)

__device__ __forceinline__ void grid_barrier(unsigned epoch) {
    __syncthreads();
    if (threadIdx.x == 0) {
        __threadfence();
        atomicAdd(&g_count, 1u);
        unsigned target = epoch * NCTA;
        while (__ldcg(&g_count) < target) { __nanosleep(32); }
    }
    __syncthreads();
}

// ---------------- init: h (linear + tiled tf32), barrier counter ----------------
__global__ void init_kernel(const float* __restrict__ init_h) {
    int i = blockIdx.x * blockDim.x + threadIdx.x;
    if (i == 0) g_count = 0u;
    if (i < BATCH * HID) {
        int b = i >> 10, j = i & 1023;
        float v = init_h[i];
        g_h[i] = v;
        g_ht_t[(j >> 6) * TILE_F + b * 68 + (j & 63)] = to_tf32(v);
    }
}

// ---------------- precompute: xproj[s][g] = emb @ Wg_x + bg ---------------------
__global__ void __launch_bounds__(256)
precompute_kernel(const float* __restrict__ emb,
                  const float* __restrict__ Wz, const float* __restrict__ Wr,
                  const float* __restrict__ Wm,
                  const float* __restrict__ bz, const float* __restrict__ br,
                  const float* __restrict__ bm) {
    __shared__ float sA[128][36];
    __shared__ float sB[32][72];

    const int g = blockIdx.z;
    const float* __restrict__ W    = (g == 0) ? Wz : ((g == 1) ? Wr : Wm);
    const float* __restrict__ bias = (g == 0) ? bz : ((g == 1) ? br : bm);

    const int m0 = blockIdx.x * 128;
    const int j0 = blockIdx.y * 64;
    const int t = threadIdx.x;
    const int warp = t >> 5, lane = t & 31;
    const int wm = warp & 3, wn = warp >> 2;
    const int grp = lane >> 2, tg = lane & 3;

    float acc[2][4][4];
#pragma unroll
    for (int i = 0; i < 2; i++)
#pragma unroll
        for (int j = 0; j < 4; j++)
#pragma unroll
            for (int q = 0; q < 4; q++) acc[i][j][q] = 0.0f;

    for (int k0 = 0; k0 < INDIM; k0 += 32) {
#pragma unroll
        for (int i = 0; i < 4; i++) {
            int idx = t + i * 256;
            int r = idx >> 3, c4 = (idx & 7) * 4;
            float4 v = *(const float4*)(emb + (size_t)(m0 + r) * INDIM + k0 + c4);
            sA[r][c4 + 0] = to_tf32(v.x); sA[r][c4 + 1] = to_tf32(v.y);
            sA[r][c4 + 2] = to_tf32(v.z); sA[r][c4 + 3] = to_tf32(v.w);
        }
#pragma unroll
        for (int i = 0; i < 2; i++) {
            int idx = t + i * 256;
            int r = idx >> 4, c4 = (idx & 15) * 4;
            float4 v = *(const float4*)(W + (size_t)(k0 + r) * HID + j0 + c4);
            sB[r][c4 + 0] = to_tf32(v.x); sB[r][c4 + 1] = to_tf32(v.y);
            sB[r][c4 + 2] = to_tf32(v.z); sB[r][c4 + 3] = to_tf32(v.w);
        }
        __syncthreads();
#pragma unroll
        for (int kk = 0; kk < 4; kk++) {
            float a[2][4];
#pragma unroll
            for (int mt = 0; mt < 2; mt++) {
                int row = wm * 32 + mt * 16;
                int kc = kk * 8 + tg;
                a[mt][0] = sA[row + grp][kc];
                a[mt][1] = sA[row + grp + 8][kc];
                a[mt][2] = sA[row + grp][kc + 4];
                a[mt][3] = sA[row + grp + 8][kc + 4];
            }
            float b[4][2];
#pragma unroll
            for (int nt = 0; nt < 4; nt++) {
                int col = wn * 32 + nt * 8 + grp;
                b[nt][0] = sB[kk * 8 + tg][col];
                b[nt][1] = sB[kk * 8 + tg + 4][col];
            }
#pragma unroll
            for (int mt = 0; mt < 2; mt++)
#pragma unroll
                for (int nt = 0; nt < 4; nt++)
                    mma_tf32(acc[mt][nt], a[mt], b[nt]);
        }
        __syncthreads();
    }

#pragma unroll
    for (int mt = 0; mt < 2; mt++) {
#pragma unroll
        for (int nt = 0; nt < 4; nt++) {
            int r0 = m0 + wm * 32 + mt * 16 + grp;
            int c0 = j0 + wn * 32 + nt * 8 + tg * 2;
            float b0 = bias[c0], b1 = bias[c0 + 1];
            {
                int m = r0; int s = m >> 6, b = m & 63;
                float2 v = make_float2(acc[mt][nt][0] + b0, acc[mt][nt][1] + b1);
                *(float2*)&g_xproj[(((size_t)s * 3 + g) * BATCH + b) * HID + c0] = v;
            }
            {
                int m = r0 + 8; int s = m >> 6, b = m & 63;
                float2 v = make_float2(acc[mt][nt][2] + b0, acc[mt][nt][3] + b1);
                *(float2*)&g_xproj[(((size_t)s * 3 + g) * BATCH + b) * HID + c0] = v;
            }
        }
    }
}

// ---------------- persistent scan kernel ----------------------------------------
// 32 clusters x 4 CTAs. Stage r of the 4-stage ring is produced by cluster rank r
// via one multicast bulk copy (mask 0xF). Full barriers local per CTA (count 1 +
// tx); empty barriers cluster-scope in rank r's SMEM (count 32 = 8 warps x 4 CTAs).
// SMEM (floats): sW1 1024x17 | sW2 1024x9 | sH 4x(64x68) | sC 64x33 | 8 mbarriers
#define SW1_ELEMS (1024 * 17)
#define SW2_ELEMS (1024 * 9)
#define SH_ELEMS  (4 * TILE_F)
#define SC_ELEMS  (64 * 33)
#define SMEM_FLOATS (SW1_ELEMS + SW2_ELEMS + SH_ELEMS + SC_ELEMS)
#define SMEM_BYTES  (SMEM_FLOATS * 4 + 128)

template <int PH>
__device__ __forceinline__ void gemm_phase(const float* __restrict__ src_t,
                                           const float* __restrict__ sW,
                                           float* __restrict__ sH, float* __restrict__ sC,
                                           unsigned mbase,
                                           unsigned (&pf)[4], unsigned (&pe)[4],
                                           int t, int lane, int wm, int wn, int grp, int tg,
                                           unsigned rank) {
    float acc0[4] = {0.f, 0.f, 0.f, 0.f};
    float acc1[4] = {0.f, 0.f, 0.f, 0.f};

    // prefetch stages 0..2: every CTA posts expect_tx; owning rank issues multicast
#pragma unroll
    for (int i = 0; i < 3; i++) {
        if (t == 0) {
            mbar_expect_tx(mbase + i * 8, TILE_B);
            if (rank == (unsigned)i) {
                mbar_wait(mbase + 32 + i * 8, pe[i]);
                pe[i] ^= 1u;
                bulk_cp_mc(sH + i * TILE_F, src_t + (size_t)i * TILE_F, TILE_B, mbase + i * 8);
            }
        }
    }

#pragma unroll
    for (int kt = 0; kt < NTILE; kt++) {
        // producer slot: tile kt+3 into stage (kt+3)&3 (freed at iteration kt-1)
        if (kt + 3 < NTILE) {
            const int nb = (kt + 3) & 3;
            if (t == 0) {
                mbar_expect_tx(mbase + nb * 8, TILE_B);
                if (rank == (unsigned)nb) {
                    mbar_wait(mbase + 32 + nb * 8, pe[nb]);
                    pe[nb] ^= 1u;
                    bulk_cp_mc(sH + nb * TILE_F, src_t + (size_t)(kt + 3) * TILE_F,
                               TILE_B, mbase + nb * 8);
                }
            }
        }

        const int bc = kt & 3;
        mbar_wait(mbase + bc * 8, pf[bc]);
        pf[bc] ^= 1u;

        const float* hb = sH + bc * TILE_F;
        if ((kt & 1) == wn) {
#pragma unroll
            for (int kk = 0; kk < 8; kk++) {
                int kc = kk * 8 + tg;
                float a[4];
                a[0] = hb[(wm * 16 + grp) * 68 + kc];
                a[1] = hb[(wm * 16 + grp + 8) * 68 + kc];
                a[2] = hb[(wm * 16 + grp) * 68 + kc + 4];
                a[3] = hb[(wm * 16 + grp + 8) * 68 + kc + 4];
                int kg = kt * 64 + kk * 8;
                float b0[2];
                if (PH == 1) {
                    b0[0] = sW[(kg + tg) * 17 + grp];
                    b0[1] = sW[(kg + tg + 4) * 17 + grp];
                    float b1[2];
                    b1[0] = sW[(kg + tg) * 17 + 8 + grp];
                    b1[1] = sW[(kg + tg + 4) * 17 + 8 + grp];
                    mma_tf32(acc0, a, b0);
                    mma_tf32(acc1, a, b1);
                } else {
                    b0[0] = sW[(kg + tg) * 9 + grp];
                    b0[1] = sW[(kg + tg + 4) * 9 + grp];
                    mma_tf32(acc0, a, b0);
                }
            }
        }
        // release: arrive on owning rank's cluster-scope empty barrier
        if (lane == 0) mbar_arrive_cluster(mbase + 32 + bc * 8, (unsigned)bc);
    }

    // stage accumulators: halves at column offsets {0,16} (PH1) / {0,8} (PH2)
    if (PH == 1) {
        int r = wm * 16 + grp;
        int cb = wn * 16;
        sC[r * 33 + cb + tg * 2]          = acc0[0];
        sC[r * 33 + cb + tg * 2 + 1]      = acc0[1];
        sC[(r + 8) * 33 + cb + tg * 2]    = acc0[2];
        sC[(r + 8) * 33 + cb + tg * 2 + 1] = acc0[3];
        sC[r * 33 + cb + 8 + tg * 2]          = acc1[0];
        sC[r * 33 + cb + 8 + tg * 2 + 1]      = acc1[1];
        sC[(r + 8) * 33 + cb + 8 + tg * 2]    = acc1[2];
        sC[(r + 8) * 33 + cb + 8 + tg * 2 + 1] = acc1[3];
    } else {
        int r = wm * 16 + grp;
        int cb = wn * 8;
        sC[r * 33 + cb + tg * 2]           = acc0[0];
        sC[r * 33 + cb + tg * 2 + 1]       = acc0[1];
        sC[(r + 8) * 33 + cb + tg * 2]     = acc0[2];
        sC[(r + 8) * 33 + cb + tg * 2 + 1] = acc0[3];
    }
    __syncthreads();
}

__global__ void __launch_bounds__(256, 1) __cluster_dims__(CLUSTER, 1, 1)
scan_kernel(const float* __restrict__ Wz, const float* __restrict__ Wr,
            const float* __restrict__ Wm, float* __restrict__ out) {
    extern __shared__ float smem[];
    float* sW1 = smem;
    float* sW2 = sW1 + SW1_ELEMS;
    float* sH  = sW2 + SW2_ELEMS;
    float* sC  = sH + SH_ELEMS;
    unsigned long long* mbars = (unsigned long long*)(sC + SC_ELEMS);

    const int c = blockIdx.x;
    const int t = threadIdx.x;
    const int warp = t >> 5, lane = t & 31;
    const int grp = lane >> 2, tg = lane & 3;
    const int wm = warp & 3;
    const int wn = warp >> 2;     // k-parity split

    unsigned rank;
    asm("mov.u32 %0, %%cluster_ctarank;" : "=r"(rank));

    const int col0 = (c & 63) * 16;   // phase-1 column base within its gate
    const int colm = c * 8;           // phase-2 column base

    // mbarrier region: full[0..3] at mbase+0..24 (local), empty[0..3] at mbase+32..56
    // (stage r's empty is USED only in the rank-r CTA; all init for symmetry)
    const unsigned mbase = (unsigned)__cvta_generic_to_shared(mbars);
    if (t == 0) {
#pragma unroll
        for (int i = 0; i < 4; i++) {
            mbar_init(mbase + i * 8, 1);        // full: 1 arrival (local expect_tx) + tx
            mbar_init(mbase + 32 + i * 8, 32);  // empty: 8 warps x 4 CTAs
        }
    }
    asm volatile("fence.proxy.async.shared::cta;" ::: "memory");
    __syncthreads();
    CLUSTER_SYNC_();   // all cluster CTAs' barriers initialized before any remote use

    // ---- load weight slices into SMEM (tf32) ----
    {
        const float* Wzr = (c < 64) ? Wz : Wr;
        for (int i = t; i < 1024 * 4; i += 256) {
            int k = i >> 2, q = (i & 3) * 4;
            float4 v = *(const float4*)(Wzr + (size_t)(512 + k) * HID + col0 + q);
            float* d = sW1 + k * 17 + q;
            d[0] = to_tf32(v.x); d[1] = to_tf32(v.y);
            d[2] = to_tf32(v.z); d[3] = to_tf32(v.w);
        }
        for (int i = t; i < 1024 * 2; i += 256) {
            int k = i >> 1, q = (i & 1) * 4;
            float4 v = *(const float4*)(Wm + (size_t)(512 + k) * HID + colm + q);
            float* d = sW2 + k * 9 + q;
            d[0] = to_tf32(v.x); d[1] = to_tf32(v.y);
            d[2] = to_tf32(v.z); d[3] = to_tf32(v.w);
        }
    }
    __syncthreads();

    unsigned epoch = 0;
    unsigned pf[4] = {0u, 0u, 0u, 0u};   // full parities (consumer)
    unsigned pe[4] = {1u, 1u, 1u, 1u};   // empty parities (producer; first wait passes)

    for (int s = 0; s < SEQ; s++) {
        // =================== PHASE 1: z,r gates ===================
        gemm_phase<1>(g_ht_t, sW1, sH, sC, mbase, pf, pe, t, lane, wm, wn, grp, tg, rank);
        {
            const float* xg = g_xproj + ((size_t)s * 3 + (c < 64 ? 0 : 1)) * BATCH * HID;
            const int tile = col0 >> 6, cw = col0 & 63;
#pragma unroll
            for (int i = 0; i < 4; i++) {
                int idx = t + i * 256;
                int b = idx >> 4, j = idx & 15;
                float val = xg[(size_t)b * HID + col0 + j] + sC[b * 33 + j] + sC[b * 33 + 16 + j];
                if (c < 64) {
                    __stcg(&g_z[b * HID + col0 + j], sigmoidf_(val));
                } else {
                    float r = sigmoidf_(val);
                    float h = __ldcg(&g_h[b * HID + col0 + j]);
                    __stcg(&g_rh_t[(size_t)tile * TILE_F + b * 68 + cw + j], to_tf32(r * h));
                }
            }
        }
        grid_barrier(++epoch);

        // =================== PHASE 2: m gate + h update ===================
        gemm_phase<2>(g_rh_t, sW2, sH, sC, mbase, pf, pe, t, lane, wm, wn, grp, tg, rank);
        {
            const int tile = colm >> 6, cw = colm & 63;
#pragma unroll
            for (int i = 0; i < 2; i++) {
                int idx = t + i * 256;
                int b = idx >> 3, j = idx & 7;
                float cm = sC[b * 33 + j] + sC[b * 33 + 8 + j];
                float xm = g_xproj[(((size_t)s * 3 + 2) * BATCH + b) * HID + colm + j];
                float ht = tanhf(xm + cm);
                float z = __ldcg(&g_z[b * HID + colm + j]);
                float h = __ldcg(&g_h[b * HID + colm + j]);
                float hn = (1.0f - z) * h + z * ht;
                __stcg(&g_h[b * HID + colm + j], hn);
                __stcg(&g_ht_t[(size_t)tile * TILE_F + b * 68 + cw + j], to_tf32(hn));
                __stcg(&out[((size_t)b * SEQ + s) * HID + colm + j], hn);
            }
        }
        grid_barrier(++epoch);
    }

    CLUSTER_SYNC_();   // no CTA exits while remote arrivals may be in flight
}

// ---------------- launch ---------------------------------------------------------
extern "C" void kernel_launch(void* const* d_in, const int* in_sizes, int n_in,
                              void* d_out, int out_size) {
    const float* emb    = (const float*)d_in[0];
    const float* init_h = (const float*)d_in[1];
    const float* Wz     = (const float*)d_in[2];
    const float* bz     = (const float*)d_in[3];
    const float* Wr     = (const float*)d_in[4];
    const float* br     = (const float*)d_in[5];
    const float* Wm     = (const float*)d_in[6];
    const float* bm     = (const float*)d_in[7];
    float* out = (float*)d_out;

    static bool attr_done = false;
    if (!attr_done) {
        cudaFuncSetAttribute(scan_kernel, cudaFuncAttributeMaxDynamicSharedMemorySize,
                             SMEM_BYTES);
        attr_done = true;
    }

    init_kernel<<<(BATCH * HID + 255) / 256, 256>>>(init_h);

    dim3 pg((SEQ * BATCH) / 128, HID / 64, 3);
    precompute_kernel<<<pg, 256>>>(emb, Wz, Wr, Wm, bz, br, bm);

    scan_kernel<<<NCTA, 256, SMEM_BYTES>>>(Wz, Wr, Wm, out);
}